// round 12
// baseline (speedup 1.0000x reference)
#include <cuda_runtime.h>
#include <math.h>

#define EMB 32
#define HID 128
#define TILE 64
#define NTHR 256

typedef unsigned long long u64;

// ---- packed f32x2 helpers (sm_103a; FFMA2/FMUL2 only reachable via PTX) ----
#define FMA_F32X2(d, a, b, c) \
    asm("fma.rn.f32x2 %0, %1, %2, %3;" : "=l"(d) : "l"(a), "l"(b), "l"(c))
#define MUL_F32X2(d, a, b) \
    asm("mul.rn.f32x2 %0, %1, %2;" : "=l"(d) : "l"(a), "l"(b))

__device__ __forceinline__ u64 bcast2(float x) {
    u64 r; unsigned int u = __float_as_uint(x);
    asm("mov.b64 %0, {%1, %1};" : "=l"(r) : "r"(u));
    return r;
}
__device__ __forceinline__ u64 pack2(float lo, float hi) {
    u64 r; unsigned int a = __float_as_uint(lo), b = __float_as_uint(hi);
    asm("mov.b64 %0, {%1, %2};" : "=l"(r) : "r"(a), "r"(b));
    return r;
}
__device__ __forceinline__ float2 unpack2(u64 v) {
    unsigned int a, b;
    asm("mov.b64 {%0, %1}, %2;" : "=r"(a), "=r"(b) : "l"(v));
    float2 f; f.x = __uint_as_float(a); f.y = __uint_as_float(b);
    return f;
}
// ELU: harness tolerance is 1e-3 relative; __expf-based form is numerically
// safe here (|err| ~1e-7 per term) and avoids the branchy expm1f routine.
__device__ __forceinline__ float elu_fast(float v) {
    return (v > 0.0f) ? v : (__expf(v) - 1.0f);
}

// Nonzero  => idx buffer is int32 (JAX x64-disabled demotion).
// Zero     => idx buffer is int64 (all high words were zero).
// atomicOr is idempotent -> safe across CUDA-graph replays.
__device__ int g_any_hi = 0;

__global__ void detect_idx_kernel(const int* __restrict__ idx32) {
    // Reads words 1,3,...,262143: in-bounds for both layouts (the buffer is
    // 262144 int32 words either way). int64 layout -> these are high words,
    // all zero for indices < 2^32. int32 layout -> these are odd-position
    // concept indices in [0, 10000), nonzero with overwhelming probability.
    int found = 0;
    for (int k = blockIdx.x * blockDim.x + threadIdx.x; k < 131072;
         k += gridDim.x * blockDim.x) {
        if (idx32[2 * k + 1] != 0) found = 1;
    }
    if (found) atomicOr(&g_any_hi, 1);
}

__global__ __launch_bounds__(NTHR, 2)
void reasoner_kernel(const float* __restrict__ concepts,
                     const float* __restrict__ Wn,  const float* __restrict__ bn,
                     const float* __restrict__ Wa,  const float* __restrict__ ba,
                     const float* __restrict__ Ws1, const float* __restrict__ bs1,
                     const float* __restrict__ Ws2, const float* __restrict__ bs2,
                     const void*  __restrict__ idxp, float* __restrict__ out)
{
    // Transposed activation buffers: S[w][k*TILE + n]  (feature-major).
    // Lifecycle: S0: a -> na -> left ; S1: b ; S2: c -> right ; S3: d
    __shared__ float S[4][EMB * TILE];

    const int tid  = threadIdx.x;
    const int base = blockIdx.x * TILE;
    const bool is64 = (g_any_hi == 0);

    // ---------------- gather: a,b,c,d -> S[0..3] (transposed) ----------------
    {
        const int n = tid >> 2;      // sample 0..63
        const int w = tid & 3;       // which of a,b,c,d
        long long row;
        if (is64) row = ((const long long*)idxp)[(long long)(base + n) * 4 + w];
        else      row = (long long)((const int*)idxp)[(base + n) * 4 + w];
        const float4* src = (const float4*)(concepts + row * EMB);
        float* dst = &S[w][n];
        #pragma unroll
        for (int k4 = 0; k4 < 8; k4++) {
            float4 v = __ldg(src + k4);
            dst[(k4 * 4 + 0) * TILE] = v.x;
            dst[(k4 * 4 + 1) * TILE] = v.y;
            dst[(k4 * 4 + 2) * TILE] = v.z;
            dst[(k4 * 4 + 3) * TILE] = v.w;
        }
    }
    __syncthreads();

    // ---------------- phase A: na = a @ Wn + bn  (S0 -> S0) ----------------
    {
        const int i  = tid & 31;     // output col
        const int sg = tid >> 5;     // 8 samples per thread
        float acc[8];
        const float bv = __ldg(bn + i);
        #pragma unroll
        for (int s = 0; s < 8; s++) acc[s] = bv;
        #pragma unroll 4
        for (int k = 0; k < EMB; k++) {
            const float w = __ldg(Wn + k * EMB + i);
            const float* ar = &S[0][k * TILE + sg * 8];
            #pragma unroll
            for (int s = 0; s < 8; s++) acc[s] = fmaf(ar[s], w, acc[s]);
        }
        __syncthreads();   // all reads of a done
        #pragma unroll
        for (int s = 0; s < 8; s++) S[0][i * TILE + sg * 8 + s] = acc[s];
    }
    __syncthreads();

    // -------- phase B/C: left = im(na,b)@Wa+ba ; right = im(c,d)@Wa+ba --------
    // Thread: 2 samples x 4 cols (= 2 col-PAIRS) x {L,R}, f32x2 accumulators.
    // Broadcasts hoisted: bcast(x)*bcast(y) = bcast(x*y) via one MUL2.
    {
        const int cg = tid & 7;      // cols cg*4 .. cg*4+3
        const int sg = tid >> 3;     // samples sg*2, sg*2+1
        const float* NA = S[0];
        const float* Bv = S[1];
        const float* Cv = S[2];
        const float* Dv = S[3];

        u64 accL[2][2], accR[2][2];  // [sample][colpair], lanes = (col, col+1)
        {
            const float2 bv0 = *(const float2*)(ba + cg * 4);
            const float2 bv1 = *(const float2*)(ba + cg * 4 + 2);
            const u64 bp0 = pack2(bv0.x, bv0.y);
            const u64 bp1 = pack2(bv1.x, bv1.y);
            accL[0][0] = bp0; accL[0][1] = bp1;
            accL[1][0] = bp0; accL[1][1] = bp1;
            accR[0][0] = bp0; accR[0][1] = bp1;
            accR[1][0] = bp0; accR[1][1] = bp1;
        }

        // rows 0..31: x part (na for L, c for R)
        #pragma unroll 4
        for (int k = 0; k < EMB; k++) {
            const float2 xl = *(const float2*)&NA[k * TILE + sg * 2];
            const float2 xr = *(const float2*)&Cv[k * TILE + sg * 2];
            const ulonglong2 wv = __ldg((const ulonglong2*)(Wa + k * EMB) + cg);
            const u64 wp[2] = {wv.x, wv.y};
            const u64 aL0 = bcast2(xl.x), aL1 = bcast2(xl.y);
            const u64 aR0 = bcast2(xr.x), aR1 = bcast2(xr.y);
            #pragma unroll
            for (int p = 0; p < 2; p++) {
                FMA_F32X2(accL[0][p], aL0, wp[p], accL[0][p]);
                FMA_F32X2(accL[1][p], aL1, wp[p], accL[1][p]);
                FMA_F32X2(accR[0][p], aR0, wp[p], accR[0][p]);
                FMA_F32X2(accR[1][p], aR1, wp[p], accR[1][p]);
            }
        }
        // rows 32..63: y part (b for L, d for R)
        #pragma unroll 4
        for (int k = 0; k < EMB; k++) {
            const float2 xl = *(const float2*)&Bv[k * TILE + sg * 2];
            const float2 xr = *(const float2*)&Dv[k * TILE + sg * 2];
            const ulonglong2 wv =
                __ldg((const ulonglong2*)(Wa + (EMB + k) * EMB) + cg);
            const u64 wp[2] = {wv.x, wv.y};
            const u64 aL0 = bcast2(xl.x), aL1 = bcast2(xl.y);
            const u64 aR0 = bcast2(xr.x), aR1 = bcast2(xr.y);
            #pragma unroll
            for (int p = 0; p < 2; p++) {
                FMA_F32X2(accL[0][p], aL0, wp[p], accL[0][p]);
                FMA_F32X2(accL[1][p], aL1, wp[p], accL[1][p]);
                FMA_F32X2(accR[0][p], aR0, wp[p], accR[0][p]);
                FMA_F32X2(accR[1][p], aR1, wp[p], accR[1][p]);
            }
        }
        // rows 64..1087: outer product x_i * y_j, j tiled by 4.
        // y broadcasts hoisted to tile scope, x broadcasts to i scope;
        // a-products formed with single MUL2 (both lanes identical).
        #pragma unroll 1
        for (int jt = 0; jt < EMB; jt += 4) {
            u64 yb2[4][2], yd2[4][2];      // [jj][sample] broadcasts
            #pragma unroll
            for (int jj = 0; jj < 4; jj++) {
                const float2 yb = *(const float2*)&Bv[(jt + jj) * TILE + sg * 2];
                const float2 yd = *(const float2*)&Dv[(jt + jj) * TILE + sg * 2];
                yb2[jj][0] = bcast2(yb.x); yb2[jj][1] = bcast2(yb.y);
                yd2[jj][0] = bcast2(yd.x); yd2[jj][1] = bcast2(yd.y);
            }
            #pragma unroll 2
            for (int i = 0; i < EMB; i++) {
                const float2 xl = *(const float2*)&NA[i * TILE + sg * 2];
                const float2 xc = *(const float2*)&Cv[i * TILE + sg * 2];
                const u64 xl2[2] = {bcast2(xl.x), bcast2(xl.y)};
                const u64 xc2[2] = {bcast2(xc.x), bcast2(xc.y)};
                const ulonglong2* wrow =
                    (const ulonglong2*)(Wa + (64 + i * 32 + jt) * EMB) + cg;
                #pragma unroll
                for (int jj = 0; jj < 4; jj++) {
                    u64 aL0, aL1, aR0, aR1;
                    MUL_F32X2(aL0, xl2[0], yb2[jj][0]);
                    MUL_F32X2(aL1, xl2[1], yb2[jj][1]);
                    MUL_F32X2(aR0, xc2[0], yd2[jj][0]);
                    MUL_F32X2(aR1, xc2[1], yd2[jj][1]);
                    const ulonglong2 wv = __ldg(wrow + jj * (EMB / 4));
                    const u64 wp[2] = {wv.x, wv.y};
                    #pragma unroll
                    for (int p = 0; p < 2; p++) {
                        FMA_F32X2(accL[0][p], aL0, wp[p], accL[0][p]);
                        FMA_F32X2(accL[1][p], aL1, wp[p], accL[1][p]);
                        FMA_F32X2(accR[0][p], aR0, wp[p], accR[0][p]);
                        FMA_F32X2(accR[1][p], aR1, wp[p], accR[1][p]);
                    }
                }
            }
        }
        __syncthreads();   // all reads of na,b,c,d done
        #pragma unroll
        for (int p = 0; p < 2; p++) {
            #pragma unroll
            for (int s = 0; s < 2; s++) {
                const float2 vL = unpack2(accL[s][p]);
                const float2 vR = unpack2(accR[s][p]);
                S[0][(cg * 4 + 2 * p + 0) * TILE + sg * 2 + s] = vL.x; // left
                S[0][(cg * 4 + 2 * p + 1) * TILE + sg * 2 + s] = vL.y;
                S[2][(cg * 4 + 2 * p + 0) * TILE + sg * 2 + s] = vR.x; // right
                S[2][(cg * 4 + 2 * p + 1) * TILE + sg * 2 + s] = vR.y;
            }
        }
    }
    __syncthreads();

    // ------- phase D: h = elu(im(left,right)@Ws1+bs1); out = h@Ws2+bs2 -------
    // Thread: 4 samples x 8 cols (= 4 col-PAIRS), f32x2 accumulators.
    {
        const int cg = tid & 15;     // cols cg*8 .. cg*8+7
        const int sg = tid >> 4;     // samples sg*4 .. sg*4+3
        const float* L = S[0];
        const float* R = S[2];

        u64 h2[4][4];                // [sample][colpair]
        {
            const float4 b0 = __ldg((const float4*)(bs1 + cg * 8));
            const float4 b1 = __ldg((const float4*)(bs1 + cg * 8 + 4));
            const u64 bp[4] = {pack2(b0.x, b0.y), pack2(b0.z, b0.w),
                               pack2(b1.x, b1.y), pack2(b1.z, b1.w)};
            #pragma unroll
            for (int s = 0; s < 4; s++)
                #pragma unroll
                for (int p = 0; p < 4; p++) h2[s][p] = bp[p];
        }

        // rows 0..31: left linear
        #pragma unroll 2
        for (int k = 0; k < EMB; k++) {
            const float4 xf = *(const float4*)&L[k * TILE + sg * 4];
            const float* wr = Ws1 + k * HID + cg * 8;
            const ulonglong2 w01 = __ldg((const ulonglong2*)wr);
            const ulonglong2 w23 = __ldg((const ulonglong2*)(wr + 4));
            const u64 wp[4] = {w01.x, w01.y, w23.x, w23.y};
            const u64 a2[4] = {bcast2(xf.x), bcast2(xf.y),
                               bcast2(xf.z), bcast2(xf.w)};
            #pragma unroll
            for (int s = 0; s < 4; s++)
                #pragma unroll
                for (int p = 0; p < 4; p++)
                    FMA_F32X2(h2[s][p], a2[s], wp[p], h2[s][p]);
        }
        // rows 32..63: right linear
        #pragma unroll 2
        for (int k = 0; k < EMB; k++) {
            const float4 xf = *(const float4*)&R[k * TILE + sg * 4];
            const float* wr = Ws1 + (EMB + k) * HID + cg * 8;
            const ulonglong2 w01 = __ldg((const ulonglong2*)wr);
            const ulonglong2 w23 = __ldg((const ulonglong2*)(wr + 4));
            const u64 wp[4] = {w01.x, w01.y, w23.x, w23.y};
            const u64 a2[4] = {bcast2(xf.x), bcast2(xf.y),
                               bcast2(xf.z), bcast2(xf.w)};
            #pragma unroll
            for (int s = 0; s < 4; s++)
                #pragma unroll
                for (int p = 0; p < 4; p++)
                    FMA_F32X2(h2[s][p], a2[s], wp[p], h2[s][p]);
        }
        // rows 64..1087: outer product left_i * right_j, j tiled by 4.
        // right broadcasts hoisted to tile scope, left to i scope; products
        // via single MUL2.
        #pragma unroll 1
        for (int jt = 0; jt < EMB; jt += 4) {
            u64 rf2[4][4];               // [jj][sample] broadcasts
            #pragma unroll
            for (int jj = 0; jj < 4; jj++) {
                const float4 rf = *(const float4*)&R[(jt + jj) * TILE + sg * 4];
                rf2[jj][0] = bcast2(rf.x); rf2[jj][1] = bcast2(rf.y);
                rf2[jj][2] = bcast2(rf.z); rf2[jj][3] = bcast2(rf.w);
            }
            #pragma unroll 2
            for (int i = 0; i < EMB; i++) {
                const float4 lf = *(const float4*)&L[i * TILE + sg * 4];
                const u64 lf2[4] = {bcast2(lf.x), bcast2(lf.y),
                                    bcast2(lf.z), bcast2(lf.w)};
                const float* wbase = Ws1 + (64 + i * 32 + jt) * HID + cg * 8;
                #pragma unroll
                for (int jj = 0; jj < 4; jj++) {
                    u64 a2[4];
                    MUL_F32X2(a2[0], lf2[0], rf2[jj][0]);
                    MUL_F32X2(a2[1], lf2[1], rf2[jj][1]);
                    MUL_F32X2(a2[2], lf2[2], rf2[jj][2]);
                    MUL_F32X2(a2[3], lf2[3], rf2[jj][3]);
                    const float* wr = wbase + jj * HID;
                    const ulonglong2 w01 = __ldg((const ulonglong2*)wr);
                    const ulonglong2 w23 = __ldg((const ulonglong2*)(wr + 4));
                    const u64 wp[4] = {w01.x, w01.y, w23.x, w23.y};
                    #pragma unroll
                    for (int s = 0; s < 4; s++)
                        #pragma unroll
                        for (int p = 0; p < 4; p++)
                            FMA_F32X2(h2[s][p], a2[s], wp[p], h2[s][p]);
                }
            }
        }

        // epilogue: elu + dot with Ws2; reduce 16 cg-partials per sample via
        // shfl_xor within width-16 segments (tid = sg*16 + cg).
        float w2[8];
        #pragma unroll
        for (int u = 0; u < 8; u++) w2[u] = __ldg(Ws2 + cg * 8 + u);
        const float b2 = __ldg(bs2);
        #pragma unroll
        for (int s = 0; s < 4; s++) {
            float p = 0.0f;
            #pragma unroll
            for (int q = 0; q < 4; q++) {
                const float2 hv = unpack2(h2[s][q]);
                p = fmaf(elu_fast(hv.x), w2[2 * q + 0], p);
                p = fmaf(elu_fast(hv.y), w2[2 * q + 1], p);
            }
            p += __shfl_xor_sync(0xffffffffu, p, 8, 16);
            p += __shfl_xor_sync(0xffffffffu, p, 4, 16);
            p += __shfl_xor_sync(0xffffffffu, p, 2, 16);
            p += __shfl_xor_sync(0xffffffffu, p, 1, 16);
            if (cg == 0) out[base + sg * 4 + s] = p + b2;
        }
    }
}

extern "C" void kernel_launch(void* const* d_in, const int* in_sizes, int n_in,
                              void* d_out, int out_size) {
    const float* concepts = (const float*)d_in[0];
    const float* Wn  = (const float*)d_in[1];
    const float* bn  = (const float*)d_in[2];
    const float* Wa  = (const float*)d_in[3];
    const float* ba  = (const float*)d_in[4];
    const float* Ws1 = (const float*)d_in[5];
    const float* bs1 = (const float*)d_in[6];
    const float* Ws2 = (const float*)d_in[7];
    const float* bs2 = (const float*)d_in[8];
    const void*  idx = d_in[9];
    float* out = (float*)d_out;

    detect_idx_kernel<<<32, 256>>>((const int*)idx);
    const int blocks = out_size / TILE;   // 65536 / 64 = 1024
    reasoner_kernel<<<blocks, NTHR>>>(concepts, Wn, bn, Wa, ba,
                                      Ws1, bs1, Ws2, bs2, idx, out);
}

// round 13
// speedup vs baseline: 1.0611x; 1.0611x over previous
#include <cuda_runtime.h>
#include <math.h>

#define EMB 32
#define HID 128
#define TILE 64
#define NTHR 256

typedef unsigned long long u64;

// ---- packed f32x2 helpers (sm_103a; FFMA2/FMUL2 only reachable via PTX) ----
#define FMA_F32X2(d, a, b, c) \
    asm("fma.rn.f32x2 %0, %1, %2, %3;" : "=l"(d) : "l"(a), "l"(b), "l"(c))
#define MUL_F32X2(d, a, b) \
    asm("mul.rn.f32x2 %0, %1, %2;" : "=l"(d) : "l"(a), "l"(b))

__device__ __forceinline__ u64 bcast2(float x) {
    u64 r; unsigned int u = __float_as_uint(x);
    asm("mov.b64 %0, {%1, %1};" : "=l"(r) : "r"(u));
    return r;
}
__device__ __forceinline__ u64 pack2(float lo, float hi) {
    u64 r; unsigned int a = __float_as_uint(lo), b = __float_as_uint(hi);
    asm("mov.b64 %0, {%1, %2};" : "=l"(r) : "r"(a), "r"(b));
    return r;
}
__device__ __forceinline__ float2 unpack2(u64 v) {
    unsigned int a, b;
    asm("mov.b64 {%0, %1}, %2;" : "=r"(a), "=r"(b) : "l"(v));
    float2 f; f.x = __uint_as_float(a); f.y = __uint_as_float(b);
    return f;
}
// ELU: harness tolerance is 1e-3 relative; __expf-based form is numerically
// safe here (|err| ~1e-7 per term) and avoids the branchy expm1f routine.
__device__ __forceinline__ float elu_fast(float v) {
    return (v > 0.0f) ? v : (__expf(v) - 1.0f);
}

// Nonzero  => idx buffer is int32 (JAX x64-disabled demotion).
// Zero     => idx buffer is int64 (all high words were zero).
// atomicOr is idempotent -> safe across CUDA-graph replays.
__device__ int g_any_hi = 0;

__global__ void detect_idx_kernel(const int* __restrict__ idx32) {
    int found = 0;
    for (int k = blockIdx.x * blockDim.x + threadIdx.x; k < 131072;
         k += gridDim.x * blockDim.x) {
        if (idx32[2 * k + 1] != 0) found = 1;
    }
    if (found) atomicOr(&g_any_hi, 1);
}

__global__ __launch_bounds__(NTHR, 2)
void reasoner_kernel(const float* __restrict__ concepts,
                     const float* __restrict__ Wn,  const float* __restrict__ bn,
                     const float* __restrict__ Wa,  const float* __restrict__ ba,
                     const float* __restrict__ Ws1, const float* __restrict__ bs1,
                     const float* __restrict__ Ws2, const float* __restrict__ bs2,
                     const void*  __restrict__ idxp, float* __restrict__ out)
{
    // Transposed activation buffers: S[w][k*TILE + n]  (feature-major).
    // Lifecycle: S0: a -> na -> left ; S1: b ; S2: c -> right ; S3: d
    __shared__ float S[4][EMB * TILE];

    const int tid  = threadIdx.x;
    const int base = blockIdx.x * TILE;
    const bool is64 = (g_any_hi == 0);

    // ---------------- gather: a,b,c,d -> S[0..3] (transposed) ----------------
    {
        const int n = tid >> 2;      // sample 0..63
        const int w = tid & 3;       // which of a,b,c,d
        long long row;
        if (is64) row = ((const long long*)idxp)[(long long)(base + n) * 4 + w];
        else      row = (long long)((const int*)idxp)[(base + n) * 4 + w];
        const float4* src = (const float4*)(concepts + row * EMB);
        float* dst = &S[w][n];
        #pragma unroll
        for (int k4 = 0; k4 < 8; k4++) {
            float4 v = __ldg(src + k4);
            dst[(k4 * 4 + 0) * TILE] = v.x;
            dst[(k4 * 4 + 1) * TILE] = v.y;
            dst[(k4 * 4 + 2) * TILE] = v.z;
            dst[(k4 * 4 + 3) * TILE] = v.w;
        }
    }
    __syncthreads();

    // ---------------- phase A: na = a @ Wn + bn  (S0 -> S0) ----------------
    {
        const int i  = tid & 31;     // output col
        const int sg = tid >> 5;     // 8 samples per thread
        float acc[8];
        const float bv = __ldg(bn + i);
        #pragma unroll
        for (int s = 0; s < 8; s++) acc[s] = bv;
        #pragma unroll 4
        for (int k = 0; k < EMB; k++) {
            const float w = __ldg(Wn + k * EMB + i);
            const float* ar = &S[0][k * TILE + sg * 8];
            #pragma unroll
            for (int s = 0; s < 8; s++) acc[s] = fmaf(ar[s], w, acc[s]);
        }
        __syncthreads();   // all reads of a done
        #pragma unroll
        for (int s = 0; s < 8; s++) S[0][i * TILE + sg * 8 + s] = acc[s];
    }
    __syncthreads();

    // -------- phase B/C: left = im(na,b)@Wa+ba ; right = im(c,d)@Wa+ba --------
    // Thread: 2 samples x 4 cols (= 2 col-PAIRS) x {L,R}, f32x2 accumulators.
    // Wa rows coalesce to ~1 line per warp LDG already; left unchanged.
    {
        const int cg = tid & 7;      // cols cg*4 .. cg*4+3
        const int sg = tid >> 3;     // samples sg*2, sg*2+1
        const float* NA = S[0];
        const float* Bv = S[1];
        const float* Cv = S[2];
        const float* Dv = S[3];

        u64 accL[2][2], accR[2][2];  // [sample][colpair]
        {
            const float2 bv0 = *(const float2*)(ba + cg * 4);
            const float2 bv1 = *(const float2*)(ba + cg * 4 + 2);
            const u64 bp0 = pack2(bv0.x, bv0.y);
            const u64 bp1 = pack2(bv1.x, bv1.y);
            accL[0][0] = bp0; accL[0][1] = bp1;
            accL[1][0] = bp0; accL[1][1] = bp1;
            accR[0][0] = bp0; accR[0][1] = bp1;
            accR[1][0] = bp0; accR[1][1] = bp1;
        }

        // rows 0..31: x part (na for L, c for R)
        #pragma unroll 4
        for (int k = 0; k < EMB; k++) {
            const float2 xl = *(const float2*)&NA[k * TILE + sg * 2];
            const float2 xr = *(const float2*)&Cv[k * TILE + sg * 2];
            const ulonglong2 wv = __ldg((const ulonglong2*)(Wa + k * EMB) + cg);
            const u64 wp[2] = {wv.x, wv.y};
            const u64 aL0 = bcast2(xl.x), aL1 = bcast2(xl.y);
            const u64 aR0 = bcast2(xr.x), aR1 = bcast2(xr.y);
            #pragma unroll
            for (int p = 0; p < 2; p++) {
                FMA_F32X2(accL[0][p], aL0, wp[p], accL[0][p]);
                FMA_F32X2(accL[1][p], aL1, wp[p], accL[1][p]);
                FMA_F32X2(accR[0][p], aR0, wp[p], accR[0][p]);
                FMA_F32X2(accR[1][p], aR1, wp[p], accR[1][p]);
            }
        }
        // rows 32..63: y part (b for L, d for R)
        #pragma unroll 4
        for (int k = 0; k < EMB; k++) {
            const float2 xl = *(const float2*)&Bv[k * TILE + sg * 2];
            const float2 xr = *(const float2*)&Dv[k * TILE + sg * 2];
            const ulonglong2 wv =
                __ldg((const ulonglong2*)(Wa + (EMB + k) * EMB) + cg);
            const u64 wp[2] = {wv.x, wv.y};
            const u64 aL0 = bcast2(xl.x), aL1 = bcast2(xl.y);
            const u64 aR0 = bcast2(xr.x), aR1 = bcast2(xr.y);
            #pragma unroll
            for (int p = 0; p < 2; p++) {
                FMA_F32X2(accL[0][p], aL0, wp[p], accL[0][p]);
                FMA_F32X2(accL[1][p], aL1, wp[p], accL[1][p]);
                FMA_F32X2(accR[0][p], aR0, wp[p], accR[0][p]);
                FMA_F32X2(accR[1][p], aR1, wp[p], accR[1][p]);
            }
        }
        // rows 64..1087: outer product x_i * y_j, j tiled by 4.
        #pragma unroll 1
        for (int jt = 0; jt < EMB; jt += 4) {
            u64 yb2[4][2], yd2[4][2];
            #pragma unroll
            for (int jj = 0; jj < 4; jj++) {
                const float2 yb = *(const float2*)&Bv[(jt + jj) * TILE + sg * 2];
                const float2 yd = *(const float2*)&Dv[(jt + jj) * TILE + sg * 2];
                yb2[jj][0] = bcast2(yb.x); yb2[jj][1] = bcast2(yb.y);
                yd2[jj][0] = bcast2(yd.x); yd2[jj][1] = bcast2(yd.y);
            }
            #pragma unroll 2
            for (int i = 0; i < EMB; i++) {
                const float2 xl = *(const float2*)&NA[i * TILE + sg * 2];
                const float2 xc = *(const float2*)&Cv[i * TILE + sg * 2];
                const u64 xl2[2] = {bcast2(xl.x), bcast2(xl.y)};
                const u64 xc2[2] = {bcast2(xc.x), bcast2(xc.y)};
                const ulonglong2* wrow =
                    (const ulonglong2*)(Wa + (64 + i * 32 + jt) * EMB) + cg;
                #pragma unroll
                for (int jj = 0; jj < 4; jj++) {
                    u64 aL0, aL1, aR0, aR1;
                    MUL_F32X2(aL0, xl2[0], yb2[jj][0]);
                    MUL_F32X2(aL1, xl2[1], yb2[jj][1]);
                    MUL_F32X2(aR0, xc2[0], yd2[jj][0]);
                    MUL_F32X2(aR1, xc2[1], yd2[jj][1]);
                    const ulonglong2 wv = __ldg(wrow + jj * (EMB / 4));
                    const u64 wp[2] = {wv.x, wv.y};
                    #pragma unroll
                    for (int p = 0; p < 2; p++) {
                        FMA_F32X2(accL[0][p], aL0, wp[p], accL[0][p]);
                        FMA_F32X2(accL[1][p], aL1, wp[p], accL[1][p]);
                        FMA_F32X2(accR[0][p], aR0, wp[p], accR[0][p]);
                        FMA_F32X2(accR[1][p], aR1, wp[p], accR[1][p]);
                    }
                }
            }
        }
        __syncthreads();   // all reads of na,b,c,d done
        #pragma unroll
        for (int p = 0; p < 2; p++) {
            #pragma unroll
            for (int s = 0; s < 2; s++) {
                const float2 vL = unpack2(accL[s][p]);
                const float2 vR = unpack2(accR[s][p]);
                S[0][(cg * 4 + 2 * p + 0) * TILE + sg * 2 + s] = vL.x; // left
                S[0][(cg * 4 + 2 * p + 1) * TILE + sg * 2 + s] = vL.y;
                S[2][(cg * 4 + 2 * p + 0) * TILE + sg * 2 + s] = vR.x; // right
                S[2][(cg * 4 + 2 * p + 1) * TILE + sg * 2 + s] = vR.y;
            }
        }
    }
    __syncthreads();

    // ------- phase D: h = elu(im(left,right)@Ws1+bs1); out = h@Ws2+bs2 -------
    // REMAPPED: 8 samples x 4 cols per thread (cg 0..31, sg 0..7).
    // One warp = one sg group; its single LDG.128 per (i,jj) covers a full
    // 512B Ws1 row contiguously -> 4 wavefronts per 32 MACs/lane (was 8).
    // Activation LDS are warp-uniform broadcasts.
    {
        const int cg = tid & 31;     // cols cg*4 .. cg*4+3 (2 col-pairs)
        const int sg = tid >> 5;     // samples sg*8 .. sg*8+7
        const float* L = S[0];
        const float* R = S[2];

        u64 h2[8][2];                // [sample][colpair]
        {
            const float4 b0 = __ldg((const float4*)(bs1 + cg * 4));
            const u64 bp[2] = {pack2(b0.x, b0.y), pack2(b0.z, b0.w)};
            #pragma unroll
            for (int s = 0; s < 8; s++) {
                h2[s][0] = bp[0]; h2[s][1] = bp[1];
            }
        }

        // rows 0..31: left linear
        #pragma unroll 2
        for (int k = 0; k < EMB; k++) {
            const float4 xa = *(const float4*)&L[k * TILE + sg * 8];
            const float4 xb = *(const float4*)&L[k * TILE + sg * 8 + 4];
            const ulonglong2 wv = __ldg((const ulonglong2*)(Ws1 + k * HID) + cg);
            const u64 wp[2] = {wv.x, wv.y};
            const u64 a2[8] = {bcast2(xa.x), bcast2(xa.y), bcast2(xa.z),
                               bcast2(xa.w), bcast2(xb.x), bcast2(xb.y),
                               bcast2(xb.z), bcast2(xb.w)};
            #pragma unroll
            for (int s = 0; s < 8; s++) {
                FMA_F32X2(h2[s][0], a2[s], wp[0], h2[s][0]);
                FMA_F32X2(h2[s][1], a2[s], wp[1], h2[s][1]);
            }
        }
        // rows 32..63: right linear
        #pragma unroll 2
        for (int k = 0; k < EMB; k++) {
            const float4 xa = *(const float4*)&R[k * TILE + sg * 8];
            const float4 xb = *(const float4*)&R[k * TILE + sg * 8 + 4];
            const ulonglong2 wv =
                __ldg((const ulonglong2*)(Ws1 + (EMB + k) * HID) + cg);
            const u64 wp[2] = {wv.x, wv.y};
            const u64 a2[8] = {bcast2(xa.x), bcast2(xa.y), bcast2(xa.z),
                               bcast2(xa.w), bcast2(xb.x), bcast2(xb.y),
                               bcast2(xb.z), bcast2(xb.w)};
            #pragma unroll
            for (int s = 0; s < 8; s++) {
                FMA_F32X2(h2[s][0], a2[s], wp[0], h2[s][0]);
                FMA_F32X2(h2[s][1], a2[s], wp[1], h2[s][1]);
            }
        }
        // rows 64..1087: outer product left_i * right_j, j tiled by 2
        // (register budget: h2 32r + rf2 32r + lf2 16r + transients < 128).
        #pragma unroll 1
        for (int jt = 0; jt < EMB; jt += 2) {
            u64 rf2[2][8];               // [jj][sample] broadcasts
            #pragma unroll
            for (int jj = 0; jj < 2; jj++) {
                const float4 ra = *(const float4*)&R[(jt + jj) * TILE + sg * 8];
                const float4 rb =
                    *(const float4*)&R[(jt + jj) * TILE + sg * 8 + 4];
                rf2[jj][0] = bcast2(ra.x); rf2[jj][1] = bcast2(ra.y);
                rf2[jj][2] = bcast2(ra.z); rf2[jj][3] = bcast2(ra.w);
                rf2[jj][4] = bcast2(rb.x); rf2[jj][5] = bcast2(rb.y);
                rf2[jj][6] = bcast2(rb.z); rf2[jj][7] = bcast2(rb.w);
            }
            #pragma unroll 2
            for (int i = 0; i < EMB; i++) {
                const float4 la = *(const float4*)&L[i * TILE + sg * 8];
                const float4 lb = *(const float4*)&L[i * TILE + sg * 8 + 4];
                const u64 lf2[8] = {bcast2(la.x), bcast2(la.y), bcast2(la.z),
                                    bcast2(la.w), bcast2(lb.x), bcast2(lb.y),
                                    bcast2(lb.z), bcast2(lb.w)};
                const float* wbase = Ws1 + (64 + i * 32 + jt) * HID;
                #pragma unroll
                for (int jj = 0; jj < 2; jj++) {
                    u64 a2[8];
                    #pragma unroll
                    for (int s = 0; s < 8; s++)
                        MUL_F32X2(a2[s], lf2[s], rf2[jj][s]);
                    const ulonglong2 wv =
                        __ldg((const ulonglong2*)(wbase + jj * HID) + cg);
                    const u64 wp[2] = {wv.x, wv.y};
                    #pragma unroll
                    for (int s = 0; s < 8; s++) {
                        FMA_F32X2(h2[s][0], a2[s], wp[0], h2[s][0]);
                        FMA_F32X2(h2[s][1], a2[s], wp[1], h2[s][1]);
                    }
                }
            }
        }

        // epilogue: elu + dot with Ws2; full-warp reduction (warp = one sg
        // group; all 32 lanes hold partials for the same 8 samples).
        float w2[4];
        #pragma unroll
        for (int u = 0; u < 4; u++) w2[u] = __ldg(Ws2 + cg * 4 + u);
        const float b2 = __ldg(bs2);
        #pragma unroll
        for (int s = 0; s < 8; s++) {
            const float2 h0 = unpack2(h2[s][0]);
            const float2 h1 = unpack2(h2[s][1]);
            float p = elu_fast(h0.x) * w2[0];
            p = fmaf(elu_fast(h0.y), w2[1], p);
            p = fmaf(elu_fast(h1.x), w2[2], p);
            p = fmaf(elu_fast(h1.y), w2[3], p);
            p += __shfl_xor_sync(0xffffffffu, p, 16);
            p += __shfl_xor_sync(0xffffffffu, p, 8);
            p += __shfl_xor_sync(0xffffffffu, p, 4);
            p += __shfl_xor_sync(0xffffffffu, p, 2);
            p += __shfl_xor_sync(0xffffffffu, p, 1);
            if (cg == 0) out[base + sg * 8 + s] = p + b2;
        }
    }
}

extern "C" void kernel_launch(void* const* d_in, const int* in_sizes, int n_in,
                              void* d_out, int out_size) {
    const float* concepts = (const float*)d_in[0];
    const float* Wn  = (const float*)d_in[1];
    const float* bn  = (const float*)d_in[2];
    const float* Wa  = (const float*)d_in[3];
    const float* ba  = (const float*)d_in[4];
    const float* Ws1 = (const float*)d_in[5];
    const float* bs1 = (const float*)d_in[6];
    const float* Ws2 = (const float*)d_in[7];
    const float* bs2 = (const float*)d_in[8];
    const void*  idx = d_in[9];
    float* out = (float*)d_out;

    detect_idx_kernel<<<32, 256>>>((const int*)idx);
    const int blocks = out_size / TILE;   // 65536 / 64 = 1024
    reasoner_kernel<<<blocks, NTHR>>>(concepts, Wn, bn, Wa, ba,
                                      Ws1, bs1, Ws2, bs2, idx, out);
}